// round 14
// baseline (speedup 1.0000x reference)
#include <cuda_runtime.h>

#define NNODES 507904
#define NEDGES 4063232
#define HID 64
#define NGRAPHS 8192
#define NPG 62
#define BN_EPS 1e-5f
#define FN ((float)NNODES)
#define BKT_CAP 64
#define MTILE 64

// dynamic smem (floats):
// sAT[4096] | sWa[4096] | sWb[4096] | sB1[64] | sB2[64] | sS[64] | sT[64] | sStat[128]
#define SMEM_FLOATS (4096 + 4096 + 4096 + 64 + 64 + 64 + 64 + 128)
#define SMEM_BYTES  (SMEM_FLOATS * 4)

// -------- device scratch (no allocations allowed) --------
__device__ float g_hA[(size_t)NNODES * HID];        // activation buffer A
__device__ float g_hB[(size_t)NNODES * HID];        // activation buffer B
__device__ int4  g_bkt4[(size_t)NNODES * (BKT_CAP / 4)];  // bucket lists (16B aligned)
__device__ int   g_cur[NNODES];                     // bucket cursor == in-degree
__device__ float g_stat[6 * HID];                   // [sum0,sq0, sum1,sq1, sum2,sq2]

// packed fp32 FMA (Blackwell f32x2): d = a*b + d
__device__ __forceinline__ void ffma2(float2& d, float2 a, float2 b) {
    asm("{\n\t"
        ".reg .b64 ra, rb, rd;\n\t"
        "mov.b64 ra, {%2, %3};\n\t"
        "mov.b64 rb, {%4, %5};\n\t"
        "mov.b64 rd, {%0, %1};\n\t"
        "fma.rn.f32x2 rd, ra, rb, rd;\n\t"
        "mov.b64 {%0, %1}, rd;\n\t"
        "}"
        : "+f"(d.x), "+f"(d.y)
        : "f"(a.x), "f"(a.y), "f"(b.x), "f"(b.y));
}

// packed fp32 add (Blackwell f32x2): d = d + v
__device__ __forceinline__ void add2(float2& d, float2 v) {
    asm("{\n\t"
        ".reg .b64 rd, rv;\n\t"
        "mov.b64 rd, {%0, %1};\n\t"
        "mov.b64 rv, {%2, %3};\n\t"
        "add.rn.f32x2 rd, rd, rv;\n\t"
        "mov.b64 {%0, %1}, rd;\n\t"
        "}"
        : "+f"(d.x), "+f"(d.y)
        : "f"(v.x), "f"(v.y));
}

// -------- setup kernels --------
__global__ void k_zero() {
    int i = blockIdx.x * blockDim.x + threadIdx.x;
    if (i < NNODES) g_cur[i] = 0;
    if (i < 6 * HID) g_stat[i] = 0.f;
}

__global__ void k_scatter(const int2* __restrict__ src2, const int2* __restrict__ dst2) {
    int e = blockIdx.x * blockDim.x + threadIdx.x;
    if (e < NEDGES / 2) {
        int2 d = dst2[e];
        int2 s = src2[e];
        int p0 = atomicAdd(&g_cur[d.x], 1);
        if (p0 < BKT_CAP) ((int*)g_bkt4)[(size_t)d.x * BKT_CAP + p0] = s.x;
        int p1 = atomicAdd(&g_cur[d.y], 1);
        if (p1 < BKT_CAP) ((int*)g_bkt4)[(size_t)d.y * BKT_CAP + p1] = s.y;
    }
}

// -------- fused GIN layer (warp-pipelined, 64-node tile) --------
// 256 threads, 64 nodes/CTA, 8 warps. Warp w owns nodes m in [8w, 8w+8):
// gathers them, GEMM1s them (mt = {2w, 2w+1}), mid-stores them, GEMM2s them.
// No cross-warp sAT dependency -> only __syncwarp between phases: warps in
// the gather (memory) phase overlap warps in the GEMM (FMA) phase.
// sAT: transposed A [k][m] fp32, XOR-swizzled (64-wide):
//   float offset(k,m) = k*64 + ((((m>>2) ^ ((k>>2)&15)) << 2) | (m&3))
// Both weight matrices + biases preloaded in the prologue (one block sync).
template<int KIN, bool BNFOLD>
__global__ __launch_bounds__(256, 4) void k_mlp(
    const float* __restrict__ xin, int srcsel, int dstsel,
    const float* __restrict__ Wa, const float* __restrict__ ba,
    const float* __restrict__ Wb, const float* __restrict__ bb,
    const float* __restrict__ gamma, const float* __restrict__ beta,
    int stat_in_off, int stat_out_off)
{
    extern __shared__ float smem[];
    float* sAT   = smem;                  // 4096 floats (16 KB)
    float* sWa   = smem + 4096;           // 4096 (KIN*64 used)
    float* sWb   = sWa + 4096;            // 4096
    float* sB1   = sWb + 4096;            // 64
    float* sB2   = sB1 + 64;              // 64
    float* sS    = sB2 + 64;              // 64
    float* sT    = sS + 64;               // 64
    float* sStat = sT + 64;               // 128

    const int tid = threadIdx.x;
    const int nb = blockIdx.x * MTILE;
    const int wid = tid >> 5;             // 0..7
    const int lane = tid & 31;
    const float* __restrict__ gsrc = srcsel ? g_hB : g_hA;
    float* __restrict__ gout = dstsel ? g_hB : g_hA;

    // ---- prologue: stats zero, BN coeffs, biases, BOTH weight matrices ----
    if (tid < 128) sStat[tid] = 0.f;
    if (BNFOLD && tid < 64) {
        float sum = g_stat[stat_in_off + tid];
        float sq  = g_stat[stat_in_off + 64 + tid];
        float mean = sum / FN;
        float var  = sq / FN - mean * mean;
        float inv  = rsqrtf(var + BN_EPS);
        float s    = gamma[tid] * inv;
        sS[tid] = s;
        sT[tid] = beta[tid] - mean * s;
    }
    if (tid < 64) sB1[tid] = ba[tid];
    else if (tid >= 64 && tid < 128) sB2[tid - 64] = bb[tid - 64];
    for (int i = tid; i < KIN * 64; i += 256) sWa[i] = Wa[i];
    for (int i = tid; i < 64 * 64; i += 256) sWb[i] = Wb[i];
    __syncthreads();   // the ONLY pre-epilogue block barrier

    // ---- gather phase: warp-local (m in [8*wid, 8*wid+8)) ----
    if (KIN == 4) {
        if (lane < 8) {
            int m = wid * 8 + lane;
            int node = nb + m;
            int deg = g_cur[node]; if (deg > BKT_CAP) deg = BKT_CAP;
            const int* bkt = (const int*)&g_bkt4[(size_t)node * (BKT_CAP / 4)];
            int4 q0 = ((const int4*)bkt)[0], q1 = ((const int4*)bkt)[1];
            int idx[8] = {q0.x, q0.y, q0.z, q0.w, q1.x, q1.y, q1.z, q1.w};
            float4 own = ((const float4*)xin)[node];
            float2 a01 = make_float2(own.x, own.y);
            float2 a23 = make_float2(own.z, own.w);
            #pragma unroll
            for (int j = 0; j < 8; j++) {
                if (j < deg) {
                    float4 v = ((const float4*)xin)[idx[j]];
                    add2(a01, make_float2(v.x, v.y));
                    add2(a23, make_float2(v.z, v.w));
                }
            }
            if (deg > 8) {
                int4 q2 = ((const int4*)bkt)[2], q3 = ((const int4*)bkt)[3];
                int idx2[8] = {q2.x, q2.y, q2.z, q2.w, q3.x, q3.y, q3.z, q3.w};
                #pragma unroll
                for (int j = 0; j < 8; j++) {
                    if (j + 8 < deg) {
                        float4 v = ((const float4*)xin)[idx2[j]];
                        add2(a01, make_float2(v.x, v.y));
                        add2(a23, make_float2(v.z, v.w));
                    }
                }
                for (int j = 16; j < deg; j++) {
                    float4 v = ((const float4*)xin)[bkt[j]];
                    add2(a01, make_float2(v.x, v.y));
                    add2(a23, make_float2(v.z, v.w));
                }
            }
            // k<4 -> swz=0, group = m>>2
            int base = ((m >> 2) << 2) | (m & 3);
            sAT[0 * 64 + base] = a01.x;
            sAT[1 * 64 + base] = a01.y;
            sAT[2 * 64 + base] = a23.x;
            sAT[3 * 64 + base] = a23.y;
        }
    } else {
        const int chunk = lane & 15;   // float4 chunk: channels chunk*4..+3
        const int half  = lane >> 4;   // 0..1
        float4 sSv, sTv;
        if (BNFOLD) {
            sSv = *(const float4*)&sS[chunk * 4];
            sTv = *(const float4*)&sT[chunk * 4];
        }
        #pragma unroll 1
        for (int pass = 0; pass < 4; pass++) {
            int m = wid * 8 + pass * 2 + half;
            int node = nb + m;
            int deg = g_cur[node]; if (deg > BKT_CAP) deg = BKT_CAP;
            const int* bkt = (const int*)&g_bkt4[(size_t)node * (BKT_CAP / 4)];
            int4 q0 = ((const int4*)bkt)[0], q1 = ((const int4*)bkt)[1];
            int idx[8] = {q0.x, q0.y, q0.z, q0.w, q1.x, q1.y, q1.z, q1.w};
            float4 own = ((const float4*)(gsrc + (size_t)node * 64))[chunk];
            float2 a01 = make_float2(own.x, own.y);
            float2 a23 = make_float2(own.z, own.w);
            #pragma unroll
            for (int j = 0; j < 8; j++) {
                if (j < deg) {
                    float4 v = ((const float4*)(gsrc + (size_t)idx[j] * 64))[chunk];
                    add2(a01, make_float2(v.x, v.y));
                    add2(a23, make_float2(v.z, v.w));
                }
            }
            if (deg > 8) {
                int4 q2 = ((const int4*)bkt)[2], q3 = ((const int4*)bkt)[3];
                int idx2[8] = {q2.x, q2.y, q2.z, q2.w, q3.x, q3.y, q3.z, q3.w};
                #pragma unroll
                for (int j = 0; j < 8; j++) {
                    if (j + 8 < deg) {
                        float4 v = ((const float4*)(gsrc + (size_t)idx2[j] * 64))[chunk];
                        add2(a01, make_float2(v.x, v.y));
                        add2(a23, make_float2(v.z, v.w));
                    }
                }
                for (int j = 16; j < deg; j++) {
                    float4 v = ((const float4*)(gsrc + (size_t)bkt[j] * 64))[chunk];
                    add2(a01, make_float2(v.x, v.y));
                    add2(a23, make_float2(v.z, v.w));
                }
            }
            if (BNFOLD) {
                float fd = 1.f + (float)deg;
                float2 t01 = make_float2(fd * sTv.x, fd * sTv.y);
                float2 t23 = make_float2(fd * sTv.z, fd * sTv.w);
                ffma2(t01, a01, make_float2(sSv.x, sSv.y));
                ffma2(t23, a23, make_float2(sSv.z, sSv.w));
                a01 = t01; a23 = t23;
            }
            int mg = m >> 2, mr = m & 3;
            int k0 = chunk * 4;
            int g = mg ^ chunk;   // (k0>>2)&15 == chunk for all 4 k in this chunk
            sAT[(k0 + 0) * 64 + (g << 2) + mr] = a01.x;
            sAT[(k0 + 1) * 64 + (g << 2) + mr] = a01.y;
            sAT[(k0 + 2) * 64 + (g << 2) + mr] = a23.x;
            sAT[(k0 + 3) * 64 + (g << 2) + mr] = a23.y;
        }
    }
    __syncwarp();   // warp-local sAT ready

    const int mt = tid >> 4;   // 0..15, m_base = mt*4  (warp w -> mt {2w,2w+1})
    const int nt = tid & 15;   // 0..15, n_base = nt*4

    float2 acc[4][2];
    #pragma unroll
    for (int i = 0; i < 4; i++) { acc[i][0] = make_float2(0.f, 0.f); acc[i][1] = make_float2(0.f, 0.f); }

    // ---- GEMM1: [own 8 m x KIN] @ [KIN x 64] ----
    #pragma unroll 4
    for (int k = 0; k < KIN; k++) {
        int swz = (k >> 2) & 15;
        float4 aA = *(const float4*)&sAT[k * 64 + ((mt ^ swz) << 2)];
        float4 b  = *(const float4*)&sWa[k * 64 + nt * 4];
        float2 b0 = make_float2(b.x, b.y), b1 = make_float2(b.z, b.w);
        float am[4] = {aA.x, aA.y, aA.z, aA.w};
        #pragma unroll
        for (int i = 0; i < 4; i++) {
            float2 ai = make_float2(am[i], am[i]);
            ffma2(acc[i][0], ai, b0);
            ffma2(acc[i][1], ai, b1);
        }
    }
    __syncwarp();   // done reading own sAT columns

    // ---- mid: relu(acc + b1) -> sAT (k = mid channel, own m columns) ----
    float bj[4];
    #pragma unroll
    for (int j = 0; j < 4; j++) bj[j] = sB1[nt * 4 + j];
    #pragma unroll
    for (int j = 0; j < 4; j++) {
        int k2 = nt * 4 + j;
        int jj = j >> 1;
        float v0, v1, v2, v3;
        if (j & 1) {
            v0 = acc[0][jj].y; v1 = acc[1][jj].y; v2 = acc[2][jj].y; v3 = acc[3][jj].y;
        } else {
            v0 = acc[0][jj].x; v1 = acc[1][jj].x; v2 = acc[2][jj].x; v3 = acc[3][jj].x;
        }
        float b = bj[j];
        float4 lo = make_float4(fmaxf(v0 + b, 0.f), fmaxf(v1 + b, 0.f),
                                fmaxf(v2 + b, 0.f), fmaxf(v3 + b, 0.f));
        // (k2>>2)&15 == nt -> group = mt ^ nt (all 16 groups distinct per warp)
        *(float4*)&sAT[k2 * 64 + ((mt ^ nt) << 2)] = lo;
    }
    __syncwarp();   // warp-local mid ready

    #pragma unroll
    for (int i = 0; i < 4; i++) { acc[i][0] = make_float2(0.f, 0.f); acc[i][1] = make_float2(0.f, 0.f); }

    // ---- GEMM2: [own 8 m x 64] @ [64 x 64] ----
    #pragma unroll 8
    for (int k = 0; k < 64; k++) {
        int swz = (k >> 2) & 15;
        float4 aA = *(const float4*)&sAT[k * 64 + ((mt ^ swz) << 2)];
        float4 b  = *(const float4*)&sWb[k * 64 + nt * 4];
        float2 b0 = make_float2(b.x, b.y), b1 = make_float2(b.z, b.w);
        float am[4] = {aA.x, aA.y, aA.z, aA.w};
        #pragma unroll
        for (int i = 0; i < 4; i++) {
            float2 ai = make_float2(am[i], am[i]);
            ffma2(acc[i][0], ai, b0);
            ffma2(acc[i][1], ai, b1);
        }
    }

    float2 cj01 = make_float2(sB2[nt * 4 + 0], sB2[nt * 4 + 1]);
    float2 cj23 = make_float2(sB2[nt * 4 + 2], sB2[nt * 4 + 3]);

    // ---- epilogue: relu + store + BN stats (packed) ----
    float2 psum01 = make_float2(0.f, 0.f), psum23 = make_float2(0.f, 0.f);
    float2 psq01  = make_float2(0.f, 0.f), psq23  = make_float2(0.f, 0.f);

    #pragma unroll
    for (int i = 0; i < 4; i++) {
        add2(acc[i][0], cj01);
        add2(acc[i][1], cj23);
        float2 v01 = make_float2(fmaxf(acc[i][0].x, 0.f), fmaxf(acc[i][0].y, 0.f));
        float2 v23 = make_float2(fmaxf(acc[i][1].x, 0.f), fmaxf(acc[i][1].y, 0.f));
        size_t row = (size_t)(nb + mt * 4 + i) * 64 + (size_t)nt * 4;
        *(float4*)&gout[row] = make_float4(v01.x, v01.y, v23.x, v23.y);
        add2(psum01, v01); add2(psum23, v23);
        ffma2(psq01, v01, v01); ffma2(psq23, v23, v23);
    }

    float psum[4] = {psum01.x, psum01.y, psum23.x, psum23.y};
    float psq[4]  = {psq01.x, psq01.y, psq23.x, psq23.y};

    // reduce mt-pair within warp (tid bit4), then shared atomics
    #pragma unroll
    for (int j = 0; j < 4; j++) {
        psum[j] += __shfl_xor_sync(0xffffffffu, psum[j], 16);
        psq[j]  += __shfl_xor_sync(0xffffffffu, psq[j], 16);
    }
    if ((tid & 16) == 0) {
        #pragma unroll
        for (int j = 0; j < 4; j++) {
            atomicAdd(&sStat[nt * 4 + j], psum[j]);
            atomicAdd(&sStat[64 + nt * 4 + j], psq[j]);
        }
    }
    __syncthreads();
    if (tid < 128) atomicAdd(&g_stat[stat_out_off + tid], sStat[tid]);
}

// -------- final: BN3 + per-graph sum-pool + fc (reads g_hA) --------
__global__ __launch_bounds__(64) void k_final(
    const float* __restrict__ g3, const float* __restrict__ be3,
    const float* __restrict__ Wfc, const float* __restrict__ bfc,
    float* __restrict__ out)
{
    int g = blockIdx.x;
    int c = threadIdx.x;  // 0..63

    float sum = g_stat[4 * 64 + c];
    float sq  = g_stat[5 * 64 + c];
    float mean = sum / FN;
    float var  = sq / FN - mean * mean;
    float inv  = rsqrtf(var + BN_EPS);
    float s    = g3[c] * inv;
    float t    = be3[c] - mean * s;

    const float* base = g_hA + (size_t)g * NPG * 64;
    float acc = 0.f;
    #pragma unroll 2
    for (int i = 0; i < NPG; i++) acc += base[(size_t)i * 64 + c];
    float pool = s * acc + (float)NPG * t;

    __shared__ float red[3][64];
    red[0][c] = pool * Wfc[c * 3 + 0];
    red[1][c] = pool * Wfc[c * 3 + 1];
    red[2][c] = pool * Wfc[c * 3 + 2];
    __syncthreads();
    if (c < 3) {
        float a = 0.f;
        #pragma unroll
        for (int i = 0; i < 64; i++) a += red[c][i];
        out[(size_t)g * 3 + c] = a + bfc[c];
    }
}

// -------- launch --------
extern "C" void kernel_launch(void* const* d_in, const int* in_sizes, int n_in,
                              void* d_out, int out_size) {
    (void)in_sizes; (void)n_in; (void)out_size;
    const float* x   = (const float*)d_in[0];
    const int*   src = (const int*)d_in[1];
    const int*   dst = (const int*)d_in[2];
    const float* W1a = (const float*)d_in[4];
    const float* b1a = (const float*)d_in[5];
    const float* W1b = (const float*)d_in[6];
    const float* b1b = (const float*)d_in[7];
    const float* g1  = (const float*)d_in[8];
    const float* be1 = (const float*)d_in[9];
    const float* W2a = (const float*)d_in[10];
    const float* b2a = (const float*)d_in[11];
    const float* W2b = (const float*)d_in[12];
    const float* b2b = (const float*)d_in[13];
    const float* g2  = (const float*)d_in[14];
    const float* be2 = (const float*)d_in[15];
    const float* W3a = (const float*)d_in[16];
    const float* b3a = (const float*)d_in[17];
    const float* W3b = (const float*)d_in[18];
    const float* b3b = (const float*)d_in[19];
    const float* g3  = (const float*)d_in[20];
    const float* be3 = (const float*)d_in[21];
    const float* Wfc = (const float*)d_in[22];
    const float* bfc = (const float*)d_in[23];
    float* out = (float*)d_out;

    // opt-in >48KB dynamic smem (host attribute set — capture-safe, idempotent)
    cudaFuncSetAttribute(k_mlp<4, false>, cudaFuncAttributeMaxDynamicSharedMemorySize, SMEM_BYTES);
    cudaFuncSetAttribute(k_mlp<64, true>, cudaFuncAttributeMaxDynamicSharedMemorySize, SMEM_BYTES);

    const int TPB = 256;
    k_zero<<<(NNODES + TPB - 1) / TPB, TPB>>>();
    k_scatter<<<(NEDGES / 2 + TPB - 1) / TPB, TPB>>>((const int2*)src, (const int2*)dst);

    // layer 1: input x (4ch) -> writes A
    k_mlp<4, false><<<NNODES / MTILE, 256, SMEM_BYTES>>>(x, 0, 0, W1a, b1a, W1b, b1b, nullptr, nullptr, 0, 0);
    // layer 2: gather from A + fold BN1 -> writes B
    k_mlp<64, true><<<NNODES / MTILE, 256, SMEM_BYTES>>>(nullptr, 0, 1, W2a, b2a, W2b, b2b, g1, be1, 0, 128);
    // layer 3: gather from B + fold BN2 -> writes A
    k_mlp<64, true><<<NNODES / MTILE, 256, SMEM_BYTES>>>(nullptr, 1, 0, W3a, b3a, W3b, b3b, g2, be2, 128, 256);

    // BN3 + pool + classifier (reads A)
    k_final<<<NGRAPHS, 64>>>(g3, be3, Wfc, bfc, out);
}

// round 15
// speedup vs baseline: 1.3024x; 1.3024x over previous
#include <cuda_runtime.h>

#define NNODES 507904
#define NEDGES 4063232
#define HID 64
#define NGRAPHS 8192
#define NPG 62
#define BN_EPS 1e-5f
#define FN ((float)NNODES)
#define BKT_CAP 64
#define MTILE 128

// dynamic smem (floats): sAT[8192] | sStat[128]
#define SMEM_FLOATS (8192 + 128)
#define SMEM_BYTES  (SMEM_FLOATS * 4)

// -------- device scratch (no allocations allowed) --------
__device__ float g_hA[(size_t)NNODES * HID];        // activation buffer A
__device__ float g_hB[(size_t)NNODES * HID];        // activation buffer B
__device__ int4  g_bkt4[(size_t)NNODES * (BKT_CAP / 4)];  // bucket lists (16B aligned)
__device__ int   g_cur[NNODES];                     // bucket cursor == in-degree
__device__ float g_stat[6 * HID];                   // [sum0,sq0, sum1,sq1, sum2,sq2]

// packed fp32 FMA (Blackwell f32x2): d = a*b + d
__device__ __forceinline__ void ffma2(float2& d, float2 a, float2 b) {
    asm("{\n\t"
        ".reg .b64 ra, rb, rd;\n\t"
        "mov.b64 ra, {%2, %3};\n\t"
        "mov.b64 rb, {%4, %5};\n\t"
        "mov.b64 rd, {%0, %1};\n\t"
        "fma.rn.f32x2 rd, ra, rb, rd;\n\t"
        "mov.b64 {%0, %1}, rd;\n\t"
        "}"
        : "+f"(d.x), "+f"(d.y)
        : "f"(a.x), "f"(a.y), "f"(b.x), "f"(b.y));
}

// packed fp32 add (Blackwell f32x2): d = d + v
__device__ __forceinline__ void add2(float2& d, float2 v) {
    asm("{\n\t"
        ".reg .b64 rd, rv;\n\t"
        "mov.b64 rd, {%0, %1};\n\t"
        "mov.b64 rv, {%2, %3};\n\t"
        "add.rn.f32x2 rd, rd, rv;\n\t"
        "mov.b64 {%0, %1}, rd;\n\t"
        "}"
        : "+f"(d.x), "+f"(d.y)
        : "f"(v.x), "f"(v.y));
}

// -------- setup kernels --------
__global__ void k_zero() {
    int i = blockIdx.x * blockDim.x + threadIdx.x;
    if (i < NNODES) g_cur[i] = 0;
    if (i < 6 * HID) g_stat[i] = 0.f;
}

__global__ void k_scatter(const int2* __restrict__ src2, const int2* __restrict__ dst2) {
    int e = blockIdx.x * blockDim.x + threadIdx.x;
    if (e < NEDGES / 2) {
        int2 d = dst2[e];
        int2 s = src2[e];
        int p0 = atomicAdd(&g_cur[d.x], 1);
        if (p0 < BKT_CAP) ((int*)g_bkt4)[(size_t)d.x * BKT_CAP + p0] = s.x;
        int p1 = atomicAdd(&g_cur[d.y], 1);
        if (p1 < BKT_CAP) ((int*)g_bkt4)[(size_t)d.y * BKT_CAP + p1] = s.y;
    }
}

// -------- fused GIN layer (warp-pipelined, weights via L1 LDG) --------
// 256 threads, 128 nodes/CTA, 8 warps. Warp w owns nodes m in [16w, 16w+16):
// gathers them, GEMM1s them (mt = {2w, 2w+1}), mid-stores them, GEMM2s them.
// No cross-warp sAT dependency -> only __syncwarp between phases; warps in the
// gather (memory) phase overlap warps in the GEMM (FMA) phase.
// Weights are NOT staged in smem: Wa/Wb are 16KB, shared by all CTAs, and
// L1-resident -> float4 __ldg in the k-loops (same L1 wavefront cost as LDS).
// sAT: transposed A [k][m] fp32, XOR-swizzled:
//   float offset(k,m) = k*128 + ((((m>>2) ^ ((k>>3)&7)) << 2) | (m&3))
template<int KIN, bool BNFOLD>
__global__ __launch_bounds__(256, 4) void k_mlp(
    const float* __restrict__ xin, int srcsel, int dstsel,
    const float* __restrict__ Wa, const float* __restrict__ ba,
    const float* __restrict__ Wb, const float* __restrict__ bb,
    const float* __restrict__ gamma, const float* __restrict__ beta,
    int stat_in_off, int stat_out_off)
{
    extern __shared__ float smem[];
    float* sAT   = smem;                  // 8192 floats (32 KB)
    float* sStat = smem + 8192;           // 128

    const int tid = threadIdx.x;
    const int nb = blockIdx.x * MTILE;
    const int wid = tid >> 5;             // 0..7
    const int lane = tid & 31;
    const float* __restrict__ gsrc = srcsel ? g_hB : g_hA;
    float* __restrict__ gout = dstsel ? g_hB : g_hA;

    // ---- prologue: zero the stat accumulator (tiny; the only block barrier) ----
    if (tid < 128) sStat[tid] = 0.f;
    __syncthreads();

    // ---- gather phase: warp-local (m in [16*wid, 16*wid+16)) ----
    if (KIN == 4) {
        if (lane < 16) {
            int m = wid * 16 + lane;
            int node = nb + m;
            int deg = g_cur[node]; if (deg > BKT_CAP) deg = BKT_CAP;
            const int* bkt = (const int*)&g_bkt4[(size_t)node * (BKT_CAP / 4)];
            int4 q0 = ((const int4*)bkt)[0], q1 = ((const int4*)bkt)[1];
            int idx[8] = {q0.x, q0.y, q0.z, q0.w, q1.x, q1.y, q1.z, q1.w};
            float4 own = ((const float4*)xin)[node];
            float2 a01 = make_float2(own.x, own.y);
            float2 a23 = make_float2(own.z, own.w);
            #pragma unroll
            for (int j = 0; j < 8; j++) {
                if (j < deg) {
                    float4 v = ((const float4*)xin)[idx[j]];
                    add2(a01, make_float2(v.x, v.y));
                    add2(a23, make_float2(v.z, v.w));
                }
            }
            if (deg > 8) {
                int4 q2 = ((const int4*)bkt)[2], q3 = ((const int4*)bkt)[3];
                int idx2[8] = {q2.x, q2.y, q2.z, q2.w, q3.x, q3.y, q3.z, q3.w};
                #pragma unroll
                for (int j = 0; j < 8; j++) {
                    if (j + 8 < deg) {
                        float4 v = ((const float4*)xin)[idx2[j]];
                        add2(a01, make_float2(v.x, v.y));
                        add2(a23, make_float2(v.z, v.w));
                    }
                }
                for (int j = 16; j < deg; j++) {
                    float4 v = ((const float4*)xin)[bkt[j]];
                    add2(a01, make_float2(v.x, v.y));
                    add2(a23, make_float2(v.z, v.w));
                }
            }
            int base = ((m >> 2) << 2) | (m & 3);   // k<8 -> swz=0
            sAT[0 * 128 + base] = a01.x;
            sAT[1 * 128 + base] = a01.y;
            sAT[2 * 128 + base] = a23.x;
            sAT[3 * 128 + base] = a23.y;
        }
    } else {
        const int chunk = lane & 15;   // float4 chunk: channels chunk*4..+3
        const int half  = lane >> 4;   // 0..1
        float4 sSv, sTv;
        if (BNFOLD) {
            // inline BN coeffs for this thread's 4 channels (no smem, no barrier)
            float4 sum4 = __ldg((const float4*)&g_stat[stat_in_off] + chunk);
            float4 sq4  = __ldg((const float4*)&g_stat[stat_in_off + 64] + chunk);
            float4 gm   = __ldg((const float4*)gamma + chunk);
            float4 bt   = __ldg((const float4*)beta + chunk);
            #pragma unroll
            for (int l = 0; l < 4; l++) {
                float mean = (&sum4.x)[l] / FN;
                float var  = (&sq4.x)[l] / FN - mean * mean;
                float s    = (&gm.x)[l] * rsqrtf(var + BN_EPS);
                (&sSv.x)[l] = s;
                (&sTv.x)[l] = (&bt.x)[l] - mean * s;
            }
        }
        #pragma unroll 2
        for (int pass = 0; pass < 8; pass++) {
            int m = wid * 16 + pass * 2 + half;
            int node = nb + m;
            int deg = g_cur[node]; if (deg > BKT_CAP) deg = BKT_CAP;
            const int* bkt = (const int*)&g_bkt4[(size_t)node * (BKT_CAP / 4)];
            int4 q0 = ((const int4*)bkt)[0], q1 = ((const int4*)bkt)[1];
            int idx[8] = {q0.x, q0.y, q0.z, q0.w, q1.x, q1.y, q1.z, q1.w};
            float4 own = ((const float4*)(gsrc + (size_t)node * 64))[chunk];
            float2 a01 = make_float2(own.x, own.y);
            float2 a23 = make_float2(own.z, own.w);
            #pragma unroll
            for (int j = 0; j < 8; j++) {
                if (j < deg) {
                    float4 v = ((const float4*)(gsrc + (size_t)idx[j] * 64))[chunk];
                    add2(a01, make_float2(v.x, v.y));
                    add2(a23, make_float2(v.z, v.w));
                }
            }
            if (deg > 8) {
                int4 q2 = ((const int4*)bkt)[2], q3 = ((const int4*)bkt)[3];
                int idx2[8] = {q2.x, q2.y, q2.z, q2.w, q3.x, q3.y, q3.z, q3.w};
                #pragma unroll
                for (int j = 0; j < 8; j++) {
                    if (j + 8 < deg) {
                        float4 v = ((const float4*)(gsrc + (size_t)idx2[j] * 64))[chunk];
                        add2(a01, make_float2(v.x, v.y));
                        add2(a23, make_float2(v.z, v.w));
                    }
                }
                for (int j = 16; j < deg; j++) {
                    float4 v = ((const float4*)(gsrc + (size_t)bkt[j] * 64))[chunk];
                    add2(a01, make_float2(v.x, v.y));
                    add2(a23, make_float2(v.z, v.w));
                }
            }
            if (BNFOLD) {
                float fd = 1.f + (float)deg;
                float2 t01 = make_float2(fd * sTv.x, fd * sTv.y);
                float2 t23 = make_float2(fd * sTv.z, fd * sTv.w);
                ffma2(t01, a01, make_float2(sSv.x, sSv.y));
                ffma2(t23, a23, make_float2(sSv.z, sSv.w));
                a01 = t01; a23 = t23;
            }
            int mg = m >> 2, mr = m & 3;
            int k0 = chunk * 4;
            int g = mg ^ ((k0 >> 3) & 7);   // same swizzle group for all 4 k in chunk
            sAT[(k0 + 0) * 128 + (g << 2) + mr] = a01.x;
            sAT[(k0 + 1) * 128 + (g << 2) + mr] = a01.y;
            sAT[(k0 + 2) * 128 + (g << 2) + mr] = a23.x;
            sAT[(k0 + 3) * 128 + (g << 2) + mr] = a23.y;
        }
    }
    __syncwarp();   // warp-local sAT ready

    const int mt = tid >> 4;   // 0..15, m_base = mt*8  (warp w -> mt {2w,2w+1})
    const int nt = tid & 15;   // 0..15, n_base = nt*4

    float2 acc[8][2];
    #pragma unroll
    for (int i = 0; i < 8; i++) { acc[i][0] = make_float2(0.f, 0.f); acc[i][1] = make_float2(0.f, 0.f); }

    // ---- GEMM1: [own 16 m x KIN] @ [KIN x 64], W via L1 LDG ----
    #pragma unroll 4
    for (int k = 0; k < KIN; k++) {
        int swz = (k >> 3) & 7;
        float4 aA = *(const float4*)&sAT[k * 128 + (((2 * mt    ) ^ swz) << 2)];
        float4 aB = *(const float4*)&sAT[k * 128 + (((2 * mt + 1) ^ swz) << 2)];
        float4 b  = __ldg((const float4*)Wa + k * 16 + nt);
        float2 b0 = make_float2(b.x, b.y), b1 = make_float2(b.z, b.w);
        float am[8] = {aA.x, aA.y, aA.z, aA.w, aB.x, aB.y, aB.z, aB.w};
        #pragma unroll
        for (int i = 0; i < 8; i++) {
            float2 ai = make_float2(am[i], am[i]);
            ffma2(acc[i][0], ai, b0);
            ffma2(acc[i][1], ai, b1);
        }
    }
    __syncwarp();   // done reading own sAT columns

    // ---- mid: relu(acc + b1) -> sAT (k = mid channel, own m columns) ----
    float4 bj4 = __ldg((const float4*)ba + nt);
    const float* bj = &bj4.x;
    #pragma unroll
    for (int j = 0; j < 4; j++) {
        int k2 = nt * 4 + j;
        int jj = j >> 1;
        float v0, v1, v2, v3, v4, v5, v6, v7;
        if (j & 1) {
            v0 = acc[0][jj].y; v1 = acc[1][jj].y; v2 = acc[2][jj].y; v3 = acc[3][jj].y;
            v4 = acc[4][jj].y; v5 = acc[5][jj].y; v6 = acc[6][jj].y; v7 = acc[7][jj].y;
        } else {
            v0 = acc[0][jj].x; v1 = acc[1][jj].x; v2 = acc[2][jj].x; v3 = acc[3][jj].x;
            v4 = acc[4][jj].x; v5 = acc[5][jj].x; v6 = acc[6][jj].x; v7 = acc[7][jj].x;
        }
        float b = bj[j];
        float4 lo = make_float4(fmaxf(v0 + b, 0.f), fmaxf(v1 + b, 0.f),
                                fmaxf(v2 + b, 0.f), fmaxf(v3 + b, 0.f));
        float4 hi = make_float4(fmaxf(v4 + b, 0.f), fmaxf(v5 + b, 0.f),
                                fmaxf(v6 + b, 0.f), fmaxf(v7 + b, 0.f));
        int swz2 = (k2 >> 3) & 7;
        *(float4*)&sAT[k2 * 128 + (((2 * mt    ) ^ swz2) << 2)] = lo;
        *(float4*)&sAT[k2 * 128 + (((2 * mt + 1) ^ swz2) << 2)] = hi;
    }
    __syncwarp();   // warp-local mid ready

    #pragma unroll
    for (int i = 0; i < 8; i++) { acc[i][0] = make_float2(0.f, 0.f); acc[i][1] = make_float2(0.f, 0.f); }

    // ---- GEMM2: [own 16 m x 64] @ [64 x 64], W via L1 LDG ----
    #pragma unroll 4
    for (int k = 0; k < 64; k++) {
        int swz = (k >> 3) & 7;
        float4 aA = *(const float4*)&sAT[k * 128 + (((2 * mt    ) ^ swz) << 2)];
        float4 aB = *(const float4*)&sAT[k * 128 + (((2 * mt + 1) ^ swz) << 2)];
        float4 b  = __ldg((const float4*)Wb + k * 16 + nt);
        float2 b0 = make_float2(b.x, b.y), b1 = make_float2(b.z, b.w);
        float am[8] = {aA.x, aA.y, aA.z, aA.w, aB.x, aB.y, aB.z, aB.w};
        #pragma unroll
        for (int i = 0; i < 8; i++) {
            float2 ai = make_float2(am[i], am[i]);
            ffma2(acc[i][0], ai, b0);
            ffma2(acc[i][1], ai, b1);
        }
    }

    float4 cj4 = __ldg((const float4*)bb + nt);
    float2 cj01 = make_float2(cj4.x, cj4.y);
    float2 cj23 = make_float2(cj4.z, cj4.w);

    // ---- epilogue: relu + store + BN stats (packed) ----
    float2 psum01 = make_float2(0.f, 0.f), psum23 = make_float2(0.f, 0.f);
    float2 psq01  = make_float2(0.f, 0.f), psq23  = make_float2(0.f, 0.f);

    #pragma unroll
    for (int i = 0; i < 8; i++) {
        add2(acc[i][0], cj01);
        add2(acc[i][1], cj23);
        float2 v01 = make_float2(fmaxf(acc[i][0].x, 0.f), fmaxf(acc[i][0].y, 0.f));
        float2 v23 = make_float2(fmaxf(acc[i][1].x, 0.f), fmaxf(acc[i][1].y, 0.f));
        size_t row = (size_t)(nb + mt * 8 + i) * 64 + (size_t)nt * 4;
        *(float4*)&gout[row] = make_float4(v01.x, v01.y, v23.x, v23.y);
        add2(psum01, v01); add2(psum23, v23);
        ffma2(psq01, v01, v01); ffma2(psq23, v23, v23);
    }

    float psum[4] = {psum01.x, psum01.y, psum23.x, psum23.y};
    float psq[4]  = {psq01.x, psq01.y, psq23.x, psq23.y};

    // reduce mt-pair within warp (tid bit4), then shared atomics
    #pragma unroll
    for (int j = 0; j < 4; j++) {
        psum[j] += __shfl_xor_sync(0xffffffffu, psum[j], 16);
        psq[j]  += __shfl_xor_sync(0xffffffffu, psq[j], 16);
    }
    if ((tid & 16) == 0) {
        #pragma unroll
        for (int j = 0; j < 4; j++) {
            atomicAdd(&sStat[nt * 4 + j], psum[j]);
            atomicAdd(&sStat[64 + nt * 4 + j], psq[j]);
        }
    }
    __syncthreads();
    if (tid < 128) atomicAdd(&g_stat[stat_out_off + tid], sStat[tid]);
}

// -------- final: BN3 + per-graph sum-pool + fc (reads g_hA) --------
__global__ __launch_bounds__(64) void k_final(
    const float* __restrict__ g3, const float* __restrict__ be3,
    const float* __restrict__ Wfc, const float* __restrict__ bfc,
    float* __restrict__ out)
{
    int g = blockIdx.x;
    int c = threadIdx.x;  // 0..63

    float sum = g_stat[4 * 64 + c];
    float sq  = g_stat[5 * 64 + c];
    float mean = sum / FN;
    float var  = sq / FN - mean * mean;
    float inv  = rsqrtf(var + BN_EPS);
    float s    = g3[c] * inv;
    float t    = be3[c] - mean * s;

    const float* base = g_hA + (size_t)g * NPG * 64;
    float acc = 0.f;
    #pragma unroll 2
    for (int i = 0; i < NPG; i++) acc += base[(size_t)i * 64 + c];
    float pool = s * acc + (float)NPG * t;

    __shared__ float red[3][64];
    red[0][c] = pool * Wfc[c * 3 + 0];
    red[1][c] = pool * Wfc[c * 3 + 1];
    red[2][c] = pool * Wfc[c * 3 + 2];
    __syncthreads();
    if (c < 3) {
        float a = 0.f;
        #pragma unroll
        for (int i = 0; i < 64; i++) a += red[c][i];
        out[(size_t)g * 3 + c] = a + bfc[c];
    }
}

// -------- launch --------
extern "C" void kernel_launch(void* const* d_in, const int* in_sizes, int n_in,
                              void* d_out, int out_size) {
    (void)in_sizes; (void)n_in; (void)out_size;
    const float* x   = (const float*)d_in[0];
    const int*   src = (const int*)d_in[1];
    const int*   dst = (const int*)d_in[2];
    const float* W1a = (const float*)d_in[4];
    const float* b1a = (const float*)d_in[5];
    const float* W1b = (const float*)d_in[6];
    const float* b1b = (const float*)d_in[7];
    const float* g1  = (const float*)d_in[8];
    const float* be1 = (const float*)d_in[9];
    const float* W2a = (const float*)d_in[10];
    const float* b2a = (const float*)d_in[11];
    const float* W2b = (const float*)d_in[12];
    const float* b2b = (const float*)d_in[13];
    const float* g2  = (const float*)d_in[14];
    const float* be2 = (const float*)d_in[15];
    const float* W3a = (const float*)d_in[16];
    const float* b3a = (const float*)d_in[17];
    const float* W3b = (const float*)d_in[18];
    const float* b3b = (const float*)d_in[19];
    const float* g3  = (const float*)d_in[20];
    const float* be3 = (const float*)d_in[21];
    const float* Wfc = (const float*)d_in[22];
    const float* bfc = (const float*)d_in[23];
    float* out = (float*)d_out;

    const int TPB = 256;
    k_zero<<<(NNODES + TPB - 1) / TPB, TPB>>>();
    k_scatter<<<(NEDGES / 2 + TPB - 1) / TPB, TPB>>>((const int2*)src, (const int2*)dst);

    // layer 1: input x (4ch) -> writes A
    k_mlp<4, false><<<NNODES / MTILE, 256, SMEM_BYTES>>>(x, 0, 0, W1a, b1a, W1b, b1b, nullptr, nullptr, 0, 0);
    // layer 2: gather from A + fold BN1 -> writes B
    k_mlp<64, true><<<NNODES / MTILE, 256, SMEM_BYTES>>>(nullptr, 0, 1, W2a, b2a, W2b, b2b, g1, be1, 0, 128);
    // layer 3: gather from B + fold BN2 -> writes A
    k_mlp<64, true><<<NNODES / MTILE, 256, SMEM_BYTES>>>(nullptr, 1, 0, W3a, b3a, W3b, b3b, g2, be2, 128, 256);

    // BN3 + pool + classifier (reads A)
    k_final<<<NGRAPHS, 64>>>(g3, be3, Wfc, bfc, out);
}

// round 17
// speedup vs baseline: 1.3460x; 1.0335x over previous
#include <cuda_runtime.h>

#define NNODES 507904
#define NEDGES 4063232
#define HID 64
#define NGRAPHS 8192
#define NPG 62
#define BN_EPS 1e-5f
#define FN ((float)NNODES)
#define BKT_CAP 64
#define MTILE 128

// dynamic smem (floats): sAT[8192] | sStat[128]
#define SMEM_FLOATS (8192 + 128)
#define SMEM_BYTES  (SMEM_FLOATS * 4)

// -------- device scratch (no allocations allowed) --------
__device__ float g_hA[(size_t)NNODES * HID];        // activation buffer A
__device__ float g_hB[(size_t)NNODES * HID];        // activation buffer B
__device__ int4  g_bkt4[(size_t)NNODES * (BKT_CAP / 4)];  // bucket lists (16B aligned)
__device__ int   g_cur[NNODES];                     // bucket cursor == in-degree
__device__ float g_stat[6 * HID];                   // [sum0,sq0, sum1,sq1, sum2,sq2]

// packed fp32 FMA (Blackwell f32x2): d = a*b + d
__device__ __forceinline__ void ffma2(float2& d, float2 a, float2 b) {
    asm("{\n\t"
        ".reg .b64 ra, rb, rd;\n\t"
        "mov.b64 ra, {%2, %3};\n\t"
        "mov.b64 rb, {%4, %5};\n\t"
        "mov.b64 rd, {%0, %1};\n\t"
        "fma.rn.f32x2 rd, ra, rb, rd;\n\t"
        "mov.b64 {%0, %1}, rd;\n\t"
        "}"
        : "+f"(d.x), "+f"(d.y)
        : "f"(a.x), "f"(a.y), "f"(b.x), "f"(b.y));
}

// packed fp32 add (Blackwell f32x2): d = d + v
__device__ __forceinline__ void add2(float2& d, float2 v) {
    asm("{\n\t"
        ".reg .b64 rd, rv;\n\t"
        "mov.b64 rd, {%0, %1};\n\t"
        "mov.b64 rv, {%2, %3};\n\t"
        "add.rn.f32x2 rd, rd, rv;\n\t"
        "mov.b64 {%0, %1}, rd;\n\t"
        "}"
        : "+f"(d.x), "+f"(d.y)
        : "f"(v.x), "f"(v.y));
}

// L2 evict-last policy (created once per gather thread)
__device__ __forceinline__ unsigned long long mk_evict_last_policy() {
    unsigned long long pol;
    asm("createpolicy.fractional.L2::evict_last.b64 %0, 1.0;" : "=l"(pol));
    return pol;
}
// gather read with cache-hint policy: keep the (reused ~8x) activation buffer in L2
__device__ __forceinline__ float4 ldg_el4(const float* p, unsigned long long pol) {
    float4 v;
    asm("ld.global.nc.L2::cache_hint.v4.f32 {%0,%1,%2,%3}, [%4], %5;"
        : "=f"(v.x), "=f"(v.y), "=f"(v.z), "=f"(v.w) : "l"(p), "l"(pol));
    return v;
}
// streaming read (read-once bucket lists): evict-first
__device__ __forceinline__ int4 ldg_cs4(const int4* p) {
    int4 v;
    asm("ld.global.cs.v4.s32 {%0,%1,%2,%3}, [%4];"
        : "=r"(v.x), "=r"(v.y), "=r"(v.z), "=r"(v.w) : "l"(p));
    return v;
}
// streaming store (dead-for-this-kernel output): evict-first
__device__ __forceinline__ void stg_cs4(float* p, float4 v) {
    asm volatile("st.global.cs.v4.f32 [%0], {%1,%2,%3,%4};"
        :: "l"(p), "f"(v.x), "f"(v.y), "f"(v.z), "f"(v.w) : "memory");
}

// -------- setup kernels --------
__global__ void k_zero() {
    int i = blockIdx.x * blockDim.x + threadIdx.x;
    if (i < NNODES) g_cur[i] = 0;
    if (i < 6 * HID) g_stat[i] = 0.f;
}

__global__ void k_scatter(const int2* __restrict__ src2, const int2* __restrict__ dst2) {
    int e = blockIdx.x * blockDim.x + threadIdx.x;
    if (e < NEDGES / 2) {
        int2 d = dst2[e];
        int2 s = src2[e];
        int p0 = atomicAdd(&g_cur[d.x], 1);
        if (p0 < BKT_CAP) ((int*)g_bkt4)[(size_t)d.x * BKT_CAP + p0] = s.x;
        int p1 = atomicAdd(&g_cur[d.y], 1);
        if (p1 < BKT_CAP) ((int*)g_bkt4)[(size_t)d.y * BKT_CAP + p1] = s.y;
    }
}

// -------- fused GIN layer (warp-pipelined, weights via L1 LDG) --------
// 256 threads, 128 nodes/CTA, 8 warps. Warp w owns nodes m in [16w, 16w+16):
// gathers them, GEMM1s them (mt = {2w, 2w+1}), mid-stores them, GEMM2s them.
// Only __syncwarp between phases. Weights via float4 __ldg (L1-resident).
// Cache policy: gather reads evict_last (L2-pin the reused buffer, via
// createpolicy + cache_hint), bucket reads + output stores evict-first.
// sAT: transposed A [k][m] fp32, XOR-swizzled:
//   float offset(k,m) = k*128 + ((((m>>2) ^ ((k>>3)&7)) << 2) | (m&3))
template<int KIN, bool BNFOLD>
__global__ __launch_bounds__(256, 4) void k_mlp(
    const float* __restrict__ xin, int srcsel, int dstsel,
    const float* __restrict__ Wa, const float* __restrict__ ba,
    const float* __restrict__ Wb, const float* __restrict__ bb,
    const float* __restrict__ gamma, const float* __restrict__ beta,
    int stat_in_off, int stat_out_off)
{
    extern __shared__ float smem[];
    float* sAT   = smem;                  // 8192 floats (32 KB)
    float* sStat = smem + 8192;           // 128

    const int tid = threadIdx.x;
    const int nb = blockIdx.x * MTILE;
    const int wid = tid >> 5;             // 0..7
    const int lane = tid & 31;
    const float* __restrict__ gsrc = srcsel ? g_hB : g_hA;
    float* __restrict__ gout = dstsel ? g_hB : g_hA;

    // ---- prologue: zero the stat accumulator (tiny; the only block barrier) ----
    if (tid < 128) sStat[tid] = 0.f;
    __syncthreads();

    // ---- gather phase: warp-local (m in [16*wid, 16*wid+16)) ----
    if (KIN == 4) {
        if (lane < 16) {
            const unsigned long long pol = mk_evict_last_policy();
            int m = wid * 16 + lane;
            int node = nb + m;
            int deg = g_cur[node]; if (deg > BKT_CAP) deg = BKT_CAP;
            const int4* bq = &g_bkt4[(size_t)node * (BKT_CAP / 4)];
            int4 q0 = ldg_cs4(bq), q1 = ldg_cs4(bq + 1);
            int idx[8] = {q0.x, q0.y, q0.z, q0.w, q1.x, q1.y, q1.z, q1.w};
            float4 own = ldg_el4(xin + (size_t)node * 4, pol);
            float2 a01 = make_float2(own.x, own.y);
            float2 a23 = make_float2(own.z, own.w);
            #pragma unroll
            for (int j = 0; j < 8; j++) {
                if (j < deg) {
                    float4 v = ldg_el4(xin + (size_t)idx[j] * 4, pol);
                    add2(a01, make_float2(v.x, v.y));
                    add2(a23, make_float2(v.z, v.w));
                }
            }
            if (deg > 8) {
                int4 q2 = ldg_cs4(bq + 2), q3 = ldg_cs4(bq + 3);
                int idx2[8] = {q2.x, q2.y, q2.z, q2.w, q3.x, q3.y, q3.z, q3.w};
                #pragma unroll
                for (int j = 0; j < 8; j++) {
                    if (j + 8 < deg) {
                        float4 v = ldg_el4(xin + (size_t)idx2[j] * 4, pol);
                        add2(a01, make_float2(v.x, v.y));
                        add2(a23, make_float2(v.z, v.w));
                    }
                }
                for (int j = 16; j < deg; j++) {
                    float4 v = ldg_el4(xin + (size_t)((const int*)bq)[j] * 4, pol);
                    add2(a01, make_float2(v.x, v.y));
                    add2(a23, make_float2(v.z, v.w));
                }
            }
            int base = ((m >> 2) << 2) | (m & 3);   // k<8 -> swz=0
            sAT[0 * 128 + base] = a01.x;
            sAT[1 * 128 + base] = a01.y;
            sAT[2 * 128 + base] = a23.x;
            sAT[3 * 128 + base] = a23.y;
        }
    } else {
        const unsigned long long pol = mk_evict_last_policy();
        const int chunk = lane & 15;   // float4 chunk: channels chunk*4..+3
        const int half  = lane >> 4;   // 0..1
        float4 sSv, sTv;
        if (BNFOLD) {
            // inline BN coeffs for this thread's 4 channels (no smem, no barrier)
            float4 sum4 = __ldg((const float4*)&g_stat[stat_in_off] + chunk);
            float4 sq4  = __ldg((const float4*)&g_stat[stat_in_off + 64] + chunk);
            float4 gm   = __ldg((const float4*)gamma + chunk);
            float4 bt   = __ldg((const float4*)beta + chunk);
            #pragma unroll
            for (int l = 0; l < 4; l++) {
                float mean = (&sum4.x)[l] / FN;
                float var  = (&sq4.x)[l] / FN - mean * mean;
                float s    = (&gm.x)[l] * rsqrtf(var + BN_EPS);
                (&sSv.x)[l] = s;
                (&sTv.x)[l] = (&bt.x)[l] - mean * s;
            }
        }
        #pragma unroll 2
        for (int pass = 0; pass < 8; pass++) {
            int m = wid * 16 + pass * 2 + half;
            int node = nb + m;
            int deg = g_cur[node]; if (deg > BKT_CAP) deg = BKT_CAP;
            const int4* bq = &g_bkt4[(size_t)node * (BKT_CAP / 4)];
            int4 q0 = ldg_cs4(bq), q1 = ldg_cs4(bq + 1);
            int idx[8] = {q0.x, q0.y, q0.z, q0.w, q1.x, q1.y, q1.z, q1.w};
            float4 own = ldg_el4(gsrc + (size_t)node * 64 + chunk * 4, pol);
            float2 a01 = make_float2(own.x, own.y);
            float2 a23 = make_float2(own.z, own.w);
            #pragma unroll
            for (int j = 0; j < 8; j++) {
                if (j < deg) {
                    float4 v = ldg_el4(gsrc + (size_t)idx[j] * 64 + chunk * 4, pol);
                    add2(a01, make_float2(v.x, v.y));
                    add2(a23, make_float2(v.z, v.w));
                }
            }
            if (deg > 8) {
                int4 q2 = ldg_cs4(bq + 2), q3 = ldg_cs4(bq + 3);
                int idx2[8] = {q2.x, q2.y, q2.z, q2.w, q3.x, q3.y, q3.z, q3.w};
                #pragma unroll
                for (int j = 0; j < 8; j++) {
                    if (j + 8 < deg) {
                        float4 v = ldg_el4(gsrc + (size_t)idx2[j] * 64 + chunk * 4, pol);
                        add2(a01, make_float2(v.x, v.y));
                        add2(a23, make_float2(v.z, v.w));
                    }
                }
                for (int j = 16; j < deg; j++) {
                    float4 v = ldg_el4(gsrc + (size_t)((const int*)bq)[j] * 64 + chunk * 4, pol);
                    add2(a01, make_float2(v.x, v.y));
                    add2(a23, make_float2(v.z, v.w));
                }
            }
            if (BNFOLD) {
                float fd = 1.f + (float)deg;
                float2 t01 = make_float2(fd * sTv.x, fd * sTv.y);
                float2 t23 = make_float2(fd * sTv.z, fd * sTv.w);
                ffma2(t01, a01, make_float2(sSv.x, sSv.y));
                ffma2(t23, a23, make_float2(sSv.z, sSv.w));
                a01 = t01; a23 = t23;
            }
            int mg = m >> 2, mr = m & 3;
            int k0 = chunk * 4;
            int g = mg ^ ((k0 >> 3) & 7);   // same swizzle group for all 4 k in chunk
            sAT[(k0 + 0) * 128 + (g << 2) + mr] = a01.x;
            sAT[(k0 + 1) * 128 + (g << 2) + mr] = a01.y;
            sAT[(k0 + 2) * 128 + (g << 2) + mr] = a23.x;
            sAT[(k0 + 3) * 128 + (g << 2) + mr] = a23.y;
        }
    }
    __syncwarp();   // warp-local sAT ready

    const int mt = tid >> 4;   // 0..15, m_base = mt*8  (warp w -> mt {2w,2w+1})
    const int nt = tid & 15;   // 0..15, n_base = nt*4

    float2 acc[8][2];
    #pragma unroll
    for (int i = 0; i < 8; i++) { acc[i][0] = make_float2(0.f, 0.f); acc[i][1] = make_float2(0.f, 0.f); }

    // ---- GEMM1: [own 16 m x KIN] @ [KIN x 64], W via L1 LDG ----
    #pragma unroll 4
    for (int k = 0; k < KIN; k++) {
        int swz = (k >> 3) & 7;
        float4 aA = *(const float4*)&sAT[k * 128 + (((2 * mt    ) ^ swz) << 2)];
        float4 aB = *(const float4*)&sAT[k * 128 + (((2 * mt + 1) ^ swz) << 2)];
        float4 b  = __ldg((const float4*)Wa + k * 16 + nt);
        float2 b0 = make_float2(b.x, b.y), b1 = make_float2(b.z, b.w);
        float am[8] = {aA.x, aA.y, aA.z, aA.w, aB.x, aB.y, aB.z, aB.w};
        #pragma unroll
        for (int i = 0; i < 8; i++) {
            float2 ai = make_float2(am[i], am[i]);
            ffma2(acc[i][0], ai, b0);
            ffma2(acc[i][1], ai, b1);
        }
    }
    __syncwarp();   // done reading own sAT columns

    // ---- mid: relu(acc + b1) -> sAT (k = mid channel, own m columns) ----
    float4 bj4 = __ldg((const float4*)ba + nt);
    const float* bj = &bj4.x;
    #pragma unroll
    for (int j = 0; j < 4; j++) {
        int k2 = nt * 4 + j;
        int jj = j >> 1;
        float v0, v1, v2, v3, v4, v5, v6, v7;
        if (j & 1) {
            v0 = acc[0][jj].y; v1 = acc[1][jj].y; v2 = acc[2][jj].y; v3 = acc[3][jj].y;
            v4 = acc[4][jj].y; v5 = acc[5][jj].y; v6 = acc[6][jj].y; v7 = acc[7][jj].y;
        } else {
            v0 = acc[0][jj].x; v1 = acc[1][jj].x; v2 = acc[2][jj].x; v3 = acc[3][jj].x;
            v4 = acc[4][jj].x; v5 = acc[5][jj].x; v6 = acc[6][jj].x; v7 = acc[7][jj].x;
        }
        float b = bj[j];
        float4 lo = make_float4(fmaxf(v0 + b, 0.f), fmaxf(v1 + b, 0.f),
                                fmaxf(v2 + b, 0.f), fmaxf(v3 + b, 0.f));
        float4 hi = make_float4(fmaxf(v4 + b, 0.f), fmaxf(v5 + b, 0.f),
                                fmaxf(v6 + b, 0.f), fmaxf(v7 + b, 0.f));
        int swz2 = (k2 >> 3) & 7;
        *(float4*)&sAT[k2 * 128 + (((2 * mt    ) ^ swz2) << 2)] = lo;
        *(float4*)&sAT[k2 * 128 + (((2 * mt + 1) ^ swz2) << 2)] = hi;
    }
    __syncwarp();   // warp-local mid ready

    #pragma unroll
    for (int i = 0; i < 8; i++) { acc[i][0] = make_float2(0.f, 0.f); acc[i][1] = make_float2(0.f, 0.f); }

    // ---- GEMM2: [own 16 m x 64] @ [64 x 64], W via L1 LDG ----
    #pragma unroll 4
    for (int k = 0; k < 64; k++) {
        int swz = (k >> 3) & 7;
        float4 aA = *(const float4*)&sAT[k * 128 + (((2 * mt    ) ^ swz) << 2)];
        float4 aB = *(const float4*)&sAT[k * 128 + (((2 * mt + 1) ^ swz) << 2)];
        float4 b  = __ldg((const float4*)Wb + k * 16 + nt);
        float2 b0 = make_float2(b.x, b.y), b1 = make_float2(b.z, b.w);
        float am[8] = {aA.x, aA.y, aA.z, aA.w, aB.x, aB.y, aB.z, aB.w};
        #pragma unroll
        for (int i = 0; i < 8; i++) {
            float2 ai = make_float2(am[i], am[i]);
            ffma2(acc[i][0], ai, b0);
            ffma2(acc[i][1], ai, b1);
        }
    }

    float4 cj4 = __ldg((const float4*)bb + nt);
    float2 cj01 = make_float2(cj4.x, cj4.y);
    float2 cj23 = make_float2(cj4.z, cj4.w);

    // ---- epilogue: relu + streaming store + BN stats (packed) ----
    float2 psum01 = make_float2(0.f, 0.f), psum23 = make_float2(0.f, 0.f);
    float2 psq01  = make_float2(0.f, 0.f), psq23  = make_float2(0.f, 0.f);

    #pragma unroll
    for (int i = 0; i < 8; i++) {
        add2(acc[i][0], cj01);
        add2(acc[i][1], cj23);
        float2 v01 = make_float2(fmaxf(acc[i][0].x, 0.f), fmaxf(acc[i][0].y, 0.f));
        float2 v23 = make_float2(fmaxf(acc[i][1].x, 0.f), fmaxf(acc[i][1].y, 0.f));
        size_t row = (size_t)(nb + mt * 8 + i) * 64 + (size_t)nt * 4;
        stg_cs4(&gout[row], make_float4(v01.x, v01.y, v23.x, v23.y));
        add2(psum01, v01); add2(psum23, v23);
        ffma2(psq01, v01, v01); ffma2(psq23, v23, v23);
    }

    float psum[4] = {psum01.x, psum01.y, psum23.x, psum23.y};
    float psq[4]  = {psq01.x, psq01.y, psq23.x, psq23.y};

    // reduce mt-pair within warp (tid bit4), then shared atomics
    #pragma unroll
    for (int j = 0; j < 4; j++) {
        psum[j] += __shfl_xor_sync(0xffffffffu, psum[j], 16);
        psq[j]  += __shfl_xor_sync(0xffffffffu, psq[j], 16);
    }
    if ((tid & 16) == 0) {
        #pragma unroll
        for (int j = 0; j < 4; j++) {
            atomicAdd(&sStat[nt * 4 + j], psum[j]);
            atomicAdd(&sStat[64 + nt * 4 + j], psq[j]);
        }
    }
    __syncthreads();
    if (tid < 128) atomicAdd(&g_stat[stat_out_off + tid], sStat[tid]);
}

// -------- final: BN3 + per-graph sum-pool + fc (reads g_hA) --------
__global__ __launch_bounds__(64) void k_final(
    const float* __restrict__ g3, const float* __restrict__ be3,
    const float* __restrict__ Wfc, const float* __restrict__ bfc,
    float* __restrict__ out)
{
    int g = blockIdx.x;
    int c = threadIdx.x;  // 0..63

    float sum = g_stat[4 * 64 + c];
    float sq  = g_stat[5 * 64 + c];
    float mean = sum / FN;
    float var  = sq / FN - mean * mean;
    float inv  = rsqrtf(var + BN_EPS);
    float s    = g3[c] * inv;
    float t    = be3[c] - mean * s;

    const float* base = g_hA + (size_t)g * NPG * 64;
    float acc = 0.f;
    #pragma unroll 2
    for (int i = 0; i < NPG; i++) acc += base[(size_t)i * 64 + c];
    float pool = s * acc + (float)NPG * t;

    __shared__ float red[3][64];
    red[0][c] = pool * Wfc[c * 3 + 0];
    red[1][c] = pool * Wfc[c * 3 + 1];
    red[2][c] = pool * Wfc[c * 3 + 2];
    __syncthreads();
    if (c < 3) {
        float a = 0.f;
        #pragma unroll
        for (int i = 0; i < 64; i++) a += red[c][i];
        out[(size_t)g * 3 + c] = a + bfc[c];
    }
}

// -------- launch --------
extern "C" void kernel_launch(void* const* d_in, const int* in_sizes, int n_in,
                              void* d_out, int out_size) {
    (void)in_sizes; (void)n_in; (void)out_size;
    const float* x   = (const float*)d_in[0];
    const int*   src = (const int*)d_in[1];
    const int*   dst = (const int*)d_in[2];
    const float* W1a = (const float*)d_in[4];
    const float* b1a = (const float*)d_in[5];
    const float* W1b = (const float*)d_in[6];
    const float* b1b = (const float*)d_in[7];
    const float* g1  = (const float*)d_in[8];
    const float* be1 = (const float*)d_in[9];
    const float* W2a = (const float*)d_in[10];
    const float* b2a = (const float*)d_in[11];
    const float* W2b = (const float*)d_in[12];
    const float* b2b = (const float*)d_in[13];
    const float* g2  = (const float*)d_in[14];
    const float* be2 = (const float*)d_in[15];
    const float* W3a = (const float*)d_in[16];
    const float* b3a = (const float*)d_in[17];
    const float* W3b = (const float*)d_in[18];
    const float* b3b = (const float*)d_in[19];
    const float* g3  = (const float*)d_in[20];
    const float* be3 = (const float*)d_in[21];
    const float* Wfc = (const float*)d_in[22];
    const float* bfc = (const float*)d_in[23];
    float* out = (float*)d_out;

    const int TPB = 256;
    k_zero<<<(NNODES + TPB - 1) / TPB, TPB>>>();
    k_scatter<<<(NEDGES / 2 + TPB - 1) / TPB, TPB>>>((const int2*)src, (const int2*)dst);

    // layer 1: input x (4ch) -> writes A
    k_mlp<4, false><<<NNODES / MTILE, 256, SMEM_BYTES>>>(x, 0, 0, W1a, b1a, W1b, b1b, nullptr, nullptr, 0, 0);
    // layer 2: gather from A + fold BN1 -> writes B
    k_mlp<64, true><<<NNODES / MTILE, 256, SMEM_BYTES>>>(nullptr, 0, 1, W2a, b2a, W2b, b2b, g1, be1, 0, 128);
    // layer 3: gather from B + fold BN2 -> writes A
    k_mlp<64, true><<<NNODES / MTILE, 256, SMEM_BYTES>>>(nullptr, 1, 0, W3a, b3a, W3b, b3b, g2, be2, 128, 256);

    // BN3 + pool + classifier (reads A)
    k_final<<<NGRAPHS, 64>>>(g3, be3, Wfc, bfc, out);
}